// round 2
// baseline (speedup 1.0000x reference)
#include <cuda_runtime.h>
#include <cstdint>

#define B_SZ   2048
#define T_SZ   60
#define F_SZ   89
#define H_SZ   1024
#define OUT_SZ 30
#define NCH    70        // k-chunks of 16: 64 (h) + 6 (x, 89->96 padded)
#define HCH    64

// ---------------- persistent scratch (__device__ globals, no allocs) --------
// Apack: h in tf32, mma-fragment order [mt(128)][k8(128)][lane(32)][v(4)]
__device__ __align__(16) uint32_t g_ap0[128 * 128 * 32 * 4];
__device__ __align__(16) uint32_t g_ap1[128 * 128 * 32 * 4];
// Bpack: U|W tf32 frags [by(32)][chunk(70)][k8(2)][g(8)][lane(32)][v(4)]
__device__ __align__(16) uint32_t g_bp[32 * 70 * 2 * 8 * 32 * 4];
// xpack: x tf32 frags [t(60)][mt(128)][k8x(12)][lane(32)][v(4)]
__device__ __align__(16) uint32_t g_xp[60 * 128 * 12 * 32 * 4];
__device__ float g_c [B_SZ * H_SZ];
__device__ float g_hl[B_SZ * H_SZ];

__device__ __forceinline__ uint32_t f2tf(float v) {
    uint32_t u;
    asm("cvt.rna.tf32.f32 %0, %1;" : "=r"(u) : "f"(v));
    return u;
}

__device__ __forceinline__ void mma_tf32(float (&d)[4], const uint4& a,
                                         uint32_t b0, uint32_t b1) {
    asm volatile(
        "mma.sync.aligned.m16n8k8.row.col.f32.tf32.tf32.f32 "
        "{%0,%1,%2,%3}, {%4,%5,%6,%7}, {%8,%9}, {%0,%1,%2,%3};"
        : "+f"(d[0]), "+f"(d[1]), "+f"(d[2]), "+f"(d[3])
        : "r"(a.x), "r"(a.y), "r"(a.z), "r"(a.w), "r"(b0), "r"(b1));
}

// ---------------- prep kernels (run once per launch, ~30us total) ----------
__global__ void zero_state() {
    const int n = B_SZ * H_SZ;   // == Apack element count
    for (int i = blockIdx.x * blockDim.x + threadIdx.x; i < n;
         i += gridDim.x * blockDim.x) {
        g_c[i]   = 0.f;
        g_ap0[i] = 0u;
    }
}

__global__ void pack_B(const float* __restrict__ U, const float* __restrict__ W) {
    int idx = blockIdx.x * 256 + threadIdx.x;          // 32*143360 exact
    int by  = idx / 143360;
    int r   = idx % 143360;
    int c   = r / 2048;
    int r2  = r & 2047;
    int k8  = r2 >> 10;
    int g   = (r2 >> 7) & 7;
    int lane = (r2 >> 2) & 31;
    int v    = r2 & 3;
    int k    = c * 16 + k8 * 8 + (lane & 3) + (v & 1) * 4;
    int ncat = g * 16 + (v >> 1) * 8 + (lane >> 2);
    int col  = (ncat >> 5) * H_SZ + by * 32 + (ncat & 31);
    float val = 0.f;
    if (k < H_SZ)              val = U[k * (4 * H_SZ) + col];
    else if (k < H_SZ + F_SZ)  val = W[(k - H_SZ) * (4 * H_SZ) + col];
    g_bp[idx] = f2tf(val);
}

__global__ void pack_x(const float* __restrict__ x) {
    int idx = blockIdx.x * 256 + threadIdx.x;          // 60*196608 exact
    int t   = idx / 196608;
    int r   = idx % 196608;
    int mt  = r / 1536;
    int r2  = r % 1536;
    int k8  = r2 >> 7;
    int lane = (r2 >> 2) & 31;
    int v    = r2 & 3;
    int row  = mt * 16 + (lane >> 2) + (v & 1) * 8;
    int k    = k8 * 8 + (lane & 3) + (v >> 1) * 4;
    float val = (k < F_SZ) ? x[(row * T_SZ + t) * F_SZ + k] : 0.f;
    g_xp[idx] = f2tf(val);
}

// ---------------- recurrent step: barrier-free fragment-streaming GEMM ------
__global__ __launch_bounds__(256, 1)
void lstm_step(const float* __restrict__ bias, int t) {
    const int bx = blockIdx.x, by = blockIdx.y;
    const int tid = threadIdx.x, lane = tid & 31, warp = tid >> 5;
    const int warpM = warp >> 1, warpN = warp & 1;

    const uint32_t* __restrict__ ap = (t & 1) ? g_ap1 : g_ap0;
    uint32_t*       __restrict__ an = (t & 1) ? g_ap0 : g_ap1;

    const int mtB = bx * 8 + warpM * 2;
    const uint32_t* aB0 = ap + mtB * 16384 + lane * 4;
    const uint32_t* aB1 = ap + (mtB + 1) * 16384 + lane * 4;
    const uint32_t* xB0 = g_xp + (t * 128 + mtB) * 1536 + lane * 4;
    const uint32_t* xB1 = g_xp + (t * 128 + mtB + 1) * 1536 + lane * 4;
    const uint32_t* bB  = g_bp + by * 143360 + (warpN * 4) * 128 + lane * 4;

    float acc[2][8][4] = {};
    uint4 aF[2][2][2];           // [buf][mi][k8]
    uint4 bF[2][2][4];           // [buf][k8][n2]

    auto fetch = [&](int c, int s) {
        if (c < HCH) {
#pragma unroll
            for (int k8 = 0; k8 < 2; k8++) {
                aF[s][0][k8] = *(const uint4*)(aB0 + (c * 2 + k8) * 128);
                aF[s][1][k8] = *(const uint4*)(aB1 + (c * 2 + k8) * 128);
            }
        } else {
            int cx = c - HCH;
#pragma unroll
            for (int k8 = 0; k8 < 2; k8++) {
                aF[s][0][k8] = *(const uint4*)(xB0 + (cx * 2 + k8) * 128);
                aF[s][1][k8] = *(const uint4*)(xB1 + (cx * 2 + k8) * 128);
            }
        }
#pragma unroll
        for (int k8 = 0; k8 < 2; k8++)
#pragma unroll
            for (int n2 = 0; n2 < 4; n2++)
                bF[s][k8][n2] = *(const uint4*)(bB + (c * 2 + k8) * 1024 + n2 * 128);
    };

    fetch(0, 0);
    for (int c = 0; c < NCH; c++) {
        const int s = c & 1;
        if (c + 1 < NCH) fetch(c + 1, s ^ 1);
#pragma unroll
        for (int k8 = 0; k8 < 2; k8++)
#pragma unroll
            for (int n2 = 0; n2 < 4; n2++) {
                uint4 b = bF[s][k8][n2];
#pragma unroll
                for (int mi = 0; mi < 2; mi++) {
                    mma_tf32(acc[mi][n2 * 2],     aF[s][mi][k8], b.x, b.y);
                    mma_tf32(acc[mi][n2 * 2 + 1], aF[s][mi][k8], b.z, b.w);
                }
            }
    }

    // ---- fused gate epilogue (two 64-row halves through shared) ----
    __shared__ float zs[64][132];
#pragma unroll
    for (int half = 0; half < 2; half++) {
        if ((warpM >> 1) == half) {
#pragma unroll
            for (int mi = 0; mi < 2; mi++) {
                int zr = (warpM & 1) * 32 + mi * 16 + (lane >> 2);
#pragma unroll
                for (int ni = 0; ni < 8; ni++) {
                    int cN = warpN * 64 + ni * 8 + (lane & 3) * 2;
                    zs[zr][cN]         = acc[mi][ni][0];
                    zs[zr][cN + 1]     = acc[mi][ni][1];
                    zs[zr + 8][cN]     = acc[mi][ni][2];
                    zs[zr + 8][cN + 1] = acc[mi][ni][3];
                }
            }
        }
        __syncthreads();
#pragma unroll
        for (int e = 0; e < 8; e++) {
            int idx = tid + e * 256;          // 64*32 elems
            int m  = idx >> 5, nl = idx & 31;
            int gm = bx * 128 + half * 64 + m;
            int hc = by * 32 + nl;
            float zi = zs[m][nl]      + bias[hc];
            float zf = zs[m][32 + nl] + bias[H_SZ + hc];
            float zg = zs[m][64 + nl] + bias[2 * H_SZ + hc];
            float zo = zs[m][96 + nl] + bias[3 * H_SZ + hc];
            float ig = 1.f / (1.f + __expf(-zi));
            float fg = 1.f / (1.f + __expf(-zf));
            float gg = fmaxf(zg, 0.f);
            float og = 1.f / (1.f + __expf(-zo));
            int   ci = gm * H_SZ + hc;
            float cn = fg * g_c[ci] + ig * gg;
            g_c[ci] = cn;
            float h = og * fmaxf(cn, 0.f);
            // write h straight into next step's fragment layout
            int mt = gm >> 4, rr = gm & 15, k8 = hc >> 3, kk = hc & 7;
            int lw = (rr & 7) * 4 + (kk & 3);
            int v  = ((kk >> 2) << 1) | (rr >> 3);
            an[mt * 16384 + k8 * 128 + lw * 4 + v] = f2tf(h);
            if (t == T_SZ - 1) g_hl[ci] = h;
        }
        __syncthreads();
    }
}

// ---------------- dense head: y = h_T @ Wd + bd -----------------------------
__global__ void head_kernel(const float* __restrict__ Wd,
                            const float* __restrict__ bd,
                            float* __restrict__ out) {
    __shared__ float hs[H_SZ];
    const int row  = blockIdx.x;
    const int tid  = threadIdx.x;
    const int lane = tid & 31;
    const int w    = tid >> 5;
    for (int i = tid; i < H_SZ; i += 256) hs[i] = g_hl[row * H_SZ + i];
    __syncthreads();
    for (int o = w; o < OUT_SZ; o += 8) {
        float s = 0.f;
        for (int k = lane; k < H_SZ; k += 32) s += hs[k] * Wd[k * OUT_SZ + o];
#pragma unroll
        for (int off = 16; off; off >>= 1)
            s += __shfl_down_sync(0xffffffffu, s, off);
        if (lane == 0) out[row * OUT_SZ + o] = s + bd[o];
    }
}

extern "C" void kernel_launch(void* const* d_in, const int* in_sizes, int n_in,
                              void* d_out, int out_size) {
    const float* x    = (const float*)d_in[0];   // [2048,60,89]
    const float* W    = (const float*)d_in[1];   // [89,4096]
    const float* U    = (const float*)d_in[2];   // [1024,4096]
    const float* bias = (const float*)d_in[3];   // [4096]
    const float* Wd   = (const float*)d_in[4];   // [1024,30]
    const float* bd   = (const float*)d_in[5];   // [30]
    float* out = (float*)d_out;                  // [2048,30,1]

    pack_B<<<17920, 256>>>(U, W);
    pack_x<<<46080, 256>>>(x);
    zero_state<<<4096, 256>>>();

    dim3 grid(B_SZ / 128, H_SZ / 32);            // 16 x 32 CTAs
    for (int t = 0; t < T_SZ; t++)
        lstm_step<<<grid, 256>>>(bias, t);

    head_kernel<<<B_SZ, 256>>>(Wd, bd, out);
}

// round 4
// speedup vs baseline: 4.4904x; 4.4904x over previous
#include <cuda_runtime.h>
#include <cstdint>

#define B_SZ   2048
#define T_SZ   60
#define F_SZ   89
#define H_SZ   1024
#define OUT_SZ 30
#define NCH    70        // k-chunks of 16: 64 (h) + 6 (x, 89->96 padded)
#define HCH    64
#define STAGES 3

// ---------------- persistent scratch (__device__ globals, no allocs) --------
// Apack: h in tf32, mma-fragment order [mt(128)][k8(128)][lane(32)][v(4)]
__device__ __align__(16) uint32_t g_ap0[128 * 128 * 32 * 4];
__device__ __align__(16) uint32_t g_ap1[128 * 128 * 32 * 4];
// Bpack: U|W tf32 frags [by(32)][chunk(70)][k8(2)][g(8)][lane(32)][v(4)]
__device__ __align__(16) uint32_t g_bp[32 * 70 * 2 * 8 * 32 * 4];
// xpack: x tf32 frags [t(60)][mt(128)][k8x(12)][lane(32)][v(4)]
__device__ __align__(16) uint32_t g_xp[60 * 128 * 12 * 32 * 4];
__device__ float g_c [B_SZ * H_SZ];
__device__ float g_hl[B_SZ * H_SZ];

__device__ __forceinline__ uint32_t f2tf(float v) {
    uint32_t u;
    asm("cvt.rna.tf32.f32 %0, %1;" : "=r"(u) : "f"(v));
    return u;
}

__device__ __forceinline__ void mma_tf32(float (&d)[4], const uint4& a,
                                         uint32_t b0, uint32_t b1) {
    asm volatile(
        "mma.sync.aligned.m16n8k8.row.col.f32.tf32.tf32.f32 "
        "{%0,%1,%2,%3}, {%4,%5,%6,%7}, {%8,%9}, {%0,%1,%2,%3};"
        : "+f"(d[0]), "+f"(d[1]), "+f"(d[2]), "+f"(d[3])
        : "r"(a.x), "r"(a.y), "r"(a.z), "r"(a.w), "r"(b0), "r"(b1));
}

__device__ __forceinline__ void cp_async16(uint32_t saddr, const void* g) {
    asm volatile("cp.async.cg.shared.global [%0], [%1], 16;\n"
                 :: "r"(saddr), "l"(g));
}

// ---------------- prep kernels (run once per launch) ------------------------
__global__ void zero_state() {
    const int n = B_SZ * H_SZ;
    for (int i = blockIdx.x * blockDim.x + threadIdx.x; i < n;
         i += gridDim.x * blockDim.x) {
        g_c[i]   = 0.f;
        g_ap0[i] = 0u;
    }
}

__global__ void pack_B(const float* __restrict__ U, const float* __restrict__ W) {
    int idx = blockIdx.x * 256 + threadIdx.x;          // 32*143360 exact
    int by  = idx / 143360;
    int r   = idx % 143360;
    int c   = r / 2048;
    int r2  = r & 2047;
    int k8  = r2 >> 10;
    int g   = (r2 >> 7) & 7;
    int lane = (r2 >> 2) & 31;
    int v    = r2 & 3;
    int k    = c * 16 + k8 * 8 + (lane & 3) + (v & 1) * 4;
    int ncat = g * 16 + (v >> 1) * 8 + (lane >> 2);
    int col  = (ncat >> 5) * H_SZ + by * 32 + (ncat & 31);
    float val = 0.f;
    if (k < H_SZ)              val = U[k * (4 * H_SZ) + col];
    else if (k < H_SZ + F_SZ)  val = W[(k - H_SZ) * (4 * H_SZ) + col];
    g_bp[idx] = f2tf(val);
}

__global__ void pack_x(const float* __restrict__ x) {
    int idx = blockIdx.x * 256 + threadIdx.x;          // 60*196608 exact
    int t   = idx / 196608;
    int r   = idx % 196608;
    int mt  = r / 1536;
    int r2  = r % 1536;
    int k8  = r2 >> 7;
    int lane = (r2 >> 2) & 31;
    int v    = r2 & 3;
    int row  = mt * 16 + (lane >> 2) + (v & 1) * 8;
    int k    = k8 * 8 + (lane & 3) + (v >> 1) * 4;
    float val = (k < F_SZ) ? x[(row * T_SZ + t) * F_SZ + k] : 0.f;
    g_xp[idx] = f2tf(val);
}

// ---------------- recurrent step: cp.async pipelined fragment GEMM ----------
__global__ __launch_bounds__(256, 2)
void lstm_step(const float* __restrict__ bias, int t) {
    const int bx = blockIdx.x, by = blockIdx.y;
    const int tid = threadIdx.x, lane = tid & 31, warp = tid >> 5;
    const int warpM = warp >> 1, warpN = warp & 1;

    const uint32_t* __restrict__ ap = (t & 1) ? g_ap1 : g_ap0;
    uint32_t*       __restrict__ an = (t & 1) ? g_ap0 : g_ap1;

    __shared__ __align__(16) union {
        uint32_t pipe[STAGES][4096];   // [stage][ A:16x128 | B:2x8x128 ]
        float    zs[64][132];
    } sm;

    const int mtB = bx * 8;
    const uint32_t* bBase = g_bp + by * 143360;
    const uint32_t  sbase = (uint32_t)__cvta_generic_to_shared(&sm.pipe[0][0]);

    // A copy indices for this thread (2 x 16B per stage)
    const int ia0 = tid, ia1 = tid + 256;        // 512 pieces of 16B
    auto issue = [&](int c, int s) {
        uint32_t sb = sbase + s * 16384;
        // --- A: 16 blocks (mt_local x k8) of 512B ---
#pragma unroll
        for (int it = 0; it < 2; it++) {
            int idx = (it ? ia1 : ia0);
            int b   = idx >> 5;                 // 0..15
            int off = idx & 31;                 // 16B units within block
            int mtl = b >> 1, k8 = b & 1;
            const uint32_t* src;
            if (c < HCH)
                src = ap + (mtB + mtl) * 16384 + (c * 2 + k8) * 128 + off * 4;
            else
                src = g_xp + (t * 128 + mtB + mtl) * 1536 +
                      ((c - HCH) * 2 + k8) * 128 + off * 4;
            cp_async16(sb + idx * 16, src);
        }
        // --- B: one contiguous 8KB chunk ---
        const uint32_t* bsrc = bBase + c * 2048;
#pragma unroll
        for (int it = 0; it < 2; it++) {
            int idx = tid + it * 256;
            cp_async16(sb + 8192 + idx * 16, bsrc + idx * 4);
        }
    };

    float acc[2][8][4] = {};

#pragma unroll
    for (int s = 0; s < STAGES - 1; s++) {
        issue(s, s);
        asm volatile("cp.async.commit_group;");
    }

    int stage = 0;
    for (int c = 0; c < NCH; c++) {
        asm volatile("cp.async.wait_group %0;" :: "n"(STAGES - 2));
        __syncthreads();

        const uint32_t* sA = sm.pipe[stage];
        const uint32_t* sB = sm.pipe[stage] + 2048;
        uint4 aF[2][2];
#pragma unroll
        for (int mi = 0; mi < 2; mi++)
#pragma unroll
            for (int k8 = 0; k8 < 2; k8++)
                aF[mi][k8] = *(const uint4*)
                    &sA[((warpM * 2 + mi) * 2 + k8) * 128 + lane * 4];
#pragma unroll
        for (int k8 = 0; k8 < 2; k8++)
#pragma unroll
            for (int n2 = 0; n2 < 4; n2++) {
                uint4 b = *(const uint4*)
                    &sB[k8 * 1024 + (warpN * 4 + n2) * 128 + lane * 4];
#pragma unroll
                for (int mi = 0; mi < 2; mi++) {
                    mma_tf32(acc[mi][n2 * 2],     aF[mi][k8], b.x, b.y);
                    mma_tf32(acc[mi][n2 * 2 + 1], aF[mi][k8], b.z, b.w);
                }
            }

        int cn = c + STAGES - 1;
        if (cn < NCH) issue(cn, cn % STAGES);
        asm volatile("cp.async.commit_group;");
        if (++stage == STAGES) stage = 0;
    }
    __syncthreads();   // pipe buffers dead; zs aliases them

    // ---- fused gate epilogue (two 64-row halves through shared) ----
#pragma unroll
    for (int half = 0; half < 2; half++) {
        if ((warpM >> 1) == half) {
#pragma unroll
            for (int mi = 0; mi < 2; mi++) {
                int zr = (warpM & 1) * 32 + mi * 16 + (lane >> 2);
#pragma unroll
                for (int ni = 0; ni < 8; ni++) {
                    int cN = warpN * 64 + ni * 8 + (lane & 3) * 2;
                    sm.zs[zr][cN]         = acc[mi][ni][0];
                    sm.zs[zr][cN + 1]     = acc[mi][ni][1];
                    sm.zs[zr + 8][cN]     = acc[mi][ni][2];
                    sm.zs[zr + 8][cN + 1] = acc[mi][ni][3];
                }
            }
        }
        __syncthreads();
#pragma unroll
        for (int e = 0; e < 8; e++) {
            int idx = tid + e * 256;          // 64*32 elems
            int m  = idx >> 5, nl = idx & 31;
            int gm = bx * 128 + half * 64 + m;
            int hc = by * 32 + nl;
            float zi = sm.zs[m][nl]      + bias[hc];
            float zf = sm.zs[m][32 + nl] + bias[H_SZ + hc];
            float zg = sm.zs[m][64 + nl] + bias[2 * H_SZ + hc];
            float zo = sm.zs[m][96 + nl] + bias[3 * H_SZ + hc];
            float ig = 1.f / (1.f + __expf(-zi));
            float fg = 1.f / (1.f + __expf(-zf));
            float gg = fmaxf(zg, 0.f);
            float og = 1.f / (1.f + __expf(-zo));
            int   ci = gm * H_SZ + hc;
            float cn = fg * g_c[ci] + ig * gg;
            g_c[ci] = cn;
            float h = og * fmaxf(cn, 0.f);
            // write h straight into next step's fragment layout
            int mt = gm >> 4, rr = gm & 15, k8 = hc >> 3, kk = hc & 7;
            int lw = (rr & 7) * 4 + (kk & 3);
            int v  = ((kk >> 2) << 1) | (rr >> 3);
            an[mt * 16384 + k8 * 128 + lw * 4 + v] = f2tf(h);
            if (t == T_SZ - 1) g_hl[ci] = h;
        }
        __syncthreads();
    }
}

// ---------------- dense head: y = h_T @ Wd + bd -----------------------------
__global__ void head_kernel(const float* __restrict__ Wd,
                            const float* __restrict__ bd,
                            float* __restrict__ out) {
    __shared__ float hs[H_SZ];
    const int row  = blockIdx.x;
    const int tid  = threadIdx.x;
    const int lane = tid & 31;
    const int w    = tid >> 5;
    for (int i = tid; i < H_SZ; i += 256) hs[i] = g_hl[row * H_SZ + i];
    __syncthreads();
    for (int o = w; o < OUT_SZ; o += 8) {
        float s = 0.f;
        for (int k = lane; k < H_SZ; k += 32) s += hs[k] * Wd[k * OUT_SZ + o];
#pragma unroll
        for (int off = 16; off; off >>= 1)
            s += __shfl_down_sync(0xffffffffu, s, off);
        if (lane == 0) out[row * OUT_SZ + o] = s + bd[o];
    }
}

extern "C" void kernel_launch(void* const* d_in, const int* in_sizes, int n_in,
                              void* d_out, int out_size) {
    const float* x    = (const float*)d_in[0];   // [2048,60,89]
    const float* W    = (const float*)d_in[1];   // [89,4096]
    const float* U    = (const float*)d_in[2];   // [1024,4096]
    const float* bias = (const float*)d_in[3];   // [4096]
    const float* Wd   = (const float*)d_in[4];   // [1024,30]
    const float* bd   = (const float*)d_in[5];   // [30]
    float* out = (float*)d_out;                  // [2048,30,1]

    pack_B<<<17920, 256>>>(U, W);
    pack_x<<<46080, 256>>>(x);
    zero_state<<<4096, 256>>>();

    dim3 grid(B_SZ / 128, H_SZ / 32);            // 16 x 32 CTAs
    for (int t = 0; t < T_SZ; t++)
        lstm_step<<<grid, 256>>>(bias, t);

    head_kernel<<<B_SZ, 256>>>(Wd, bd, out);
}

// round 5
// speedup vs baseline: 4.9234x; 1.0964x over previous
#include <cuda_runtime.h>
#include <cstdint>

#define B_SZ   2048
#define T_SZ   60
#define F_SZ   89
#define H_SZ   1024
#define OUT_SZ 30
#define NCH    35        // k-chunks of 32: 32 (h) + 3 (x, 89->96 padded)
#define HCHN   32
#define STAGES 3
#define STG_U32 8192     // 32KB per stage in uint32 units (A 4096 | B 4096)

// ---------------- persistent scratch (__device__ globals, no allocs) --------
// Apack: h in tf32, mma-fragment order [mt(128)][k8(128)][lane(32)][v(4)]
__device__ __align__(16) uint32_t g_ap0[128 * 128 * 32 * 4];
__device__ __align__(16) uint32_t g_ap1[128 * 128 * 32 * 4];
// Bpack: U|W tf32 frags [by(32)][k8glob(140)][g(8)][lane(32)][v(4)]
__device__ __align__(16) uint32_t g_bp[32 * 70 * 2 * 8 * 32 * 4];
// xpack: x tf32 frags [t(60)][mt(128)][k8x(12)][lane(32)][v(4)]
__device__ __align__(16) uint32_t g_xp[60 * 128 * 12 * 32 * 4];
__device__ float g_c [B_SZ * H_SZ];
__device__ float g_hl[B_SZ * H_SZ];

__device__ __forceinline__ uint32_t f2tf(float v) {
    uint32_t u;
    asm("cvt.rna.tf32.f32 %0, %1;" : "=r"(u) : "f"(v));
    return u;
}

__device__ __forceinline__ void mma_tf32(float (&d)[4], const uint4& a,
                                         uint32_t b0, uint32_t b1) {
    asm volatile(
        "mma.sync.aligned.m16n8k8.row.col.f32.tf32.tf32.f32 "
        "{%0,%1,%2,%3}, {%4,%5,%6,%7}, {%8,%9}, {%0,%1,%2,%3};"
        : "+f"(d[0]), "+f"(d[1]), "+f"(d[2]), "+f"(d[3])
        : "r"(a.x), "r"(a.y), "r"(a.z), "r"(a.w), "r"(b0), "r"(b1));
}

__device__ __forceinline__ void cp_async16(uint32_t saddr, const void* g) {
    asm volatile("cp.async.cg.shared.global [%0], [%1], 16;\n"
                 :: "r"(saddr), "l"(g));
}

// ---------------- prep kernels (run once per launch) ------------------------
__global__ void zero_state() {
    const int n = B_SZ * H_SZ;
    for (int i = blockIdx.x * blockDim.x + threadIdx.x; i < n;
         i += gridDim.x * blockDim.x) {
        g_c[i]   = 0.f;
        g_ap0[i] = 0u;
    }
}

__global__ void pack_B(const float* __restrict__ U, const float* __restrict__ W) {
    int idx = blockIdx.x * 256 + threadIdx.x;          // 32*143360 exact
    int by  = idx / 143360;
    int r   = idx % 143360;
    int c   = r / 2048;
    int r2  = r & 2047;
    int k8  = r2 >> 10;
    int g   = (r2 >> 7) & 7;
    int lane = (r2 >> 2) & 31;
    int v    = r2 & 3;
    int k    = c * 16 + k8 * 8 + (lane & 3) + (v & 1) * 4;
    int ncat = g * 16 + (v >> 1) * 8 + (lane >> 2);
    int col  = (ncat >> 5) * H_SZ + by * 32 + (ncat & 31);
    float val = 0.f;
    if (k < H_SZ)              val = U[k * (4 * H_SZ) + col];
    else if (k < H_SZ + F_SZ)  val = W[(k - H_SZ) * (4 * H_SZ) + col];
    g_bp[idx] = f2tf(val);
}

__global__ void pack_x(const float* __restrict__ x) {
    int idx = blockIdx.x * 256 + threadIdx.x;          // 60*196608 exact
    int t   = idx / 196608;
    int r   = idx % 196608;
    int mt  = r / 1536;
    int r2  = r % 1536;
    int k8  = r2 >> 7;
    int lane = (r2 >> 2) & 31;
    int v    = r2 & 3;
    int row  = mt * 16 + (lane >> 2) + (v & 1) * 8;
    int k    = k8 * 8 + (lane & 3) + (v >> 1) * 4;
    float val = (k < F_SZ) ? x[(row * T_SZ + t) * F_SZ + k] : 0.f;
    g_xp[idx] = f2tf(val);
}

// ---------------- recurrent step: K32 cp.async pipelined fragment GEMM ------
__global__ __launch_bounds__(256, 2)
void lstm_step(const float* __restrict__ bias, int t) {
    const int bx = blockIdx.x, by = blockIdx.y;
    const int tid = threadIdx.x, lane = tid & 31, warp = tid >> 5;
    const int warpM = warp >> 1, warpN = warp & 1;

    const uint32_t* __restrict__ ap = (t & 1) ? g_ap1 : g_ap0;
    uint32_t*       __restrict__ an = (t & 1) ? g_ap0 : g_ap1;

    extern __shared__ __align__(16) uint32_t smdyn[];   // STAGES * 32KB
    float (*zs)[132] = (float (*)[132])smdyn;           // epilogue alias

    const int mtB = bx * 8;
    const uint32_t sbase = (uint32_t)__cvta_generic_to_shared(smdyn);

    // ---- hoisted per-thread copy offsets (element units) ----
    // A: 32 blocks (8 mt x 4 k8) of 512B per stage; thread copies 4x16B.
    int aoffH[4], aoffX[4];
#pragma unroll
    for (int it = 0; it < 4; it++) {
        int idx = tid + it * 256;
        int b   = idx >> 5;              // 0..31
        int off = idx & 31;              // 16B units within 512B block
        int mtl = b >> 2, k8 = b & 3;
        aoffH[it] = (mtB + mtl) * 16384 + k8 * 128 + off * 4;
        aoffX[it] = (t * 128 + mtB + mtl) * 1536 + k8 * 128 + off * 4;
    }
    const uint32_t* bThr = g_bp + by * 143360 + tid * 4;   // + c*4096 + it*1024
    const uint32_t  sdst = sbase + tid * 16;               // + it*4096B (+16KB for B)

    auto issue = [&](int c, int s) {
        uint32_t sb = sdst + s * 32768;
        if (c < HCHN) {
            int adv = c * 512;
#pragma unroll
            for (int it = 0; it < 4; it++)
                cp_async16(sb + it * 4096, ap + aoffH[it] + adv);
        } else {
            int adv = (c - HCHN) * 512;
#pragma unroll
            for (int it = 0; it < 4; it++)
                cp_async16(sb + it * 4096, g_xp + aoffX[it] + adv);
        }
        const uint32_t* bsrc = bThr + c * 4096;
#pragma unroll
        for (int it = 0; it < 4; it++)
            cp_async16(sb + 16384 + it * 4096, bsrc + it * 1024);
    };

    float acc[2][8][4] = {};

#pragma unroll
    for (int s = 0; s < STAGES - 1; s++) {
        issue(s, s);
        asm volatile("cp.async.commit_group;");
    }

    int stage = 0;
    for (int c = 0; c < NCH; c++) {
        asm volatile("cp.async.wait_group %0;" :: "n"(STAGES - 2));
        __syncthreads();

        const uint32_t* sA = smdyn + stage * STG_U32;
        const uint32_t* sB = sA + 4096;
#pragma unroll
        for (int k8 = 0; k8 < 4; k8++) {
            uint4 aF[2];
#pragma unroll
            for (int mi = 0; mi < 2; mi++)
                aF[mi] = *(const uint4*)
                    &sA[((warpM * 2 + mi) * 4 + k8) * 128 + lane * 4];
#pragma unroll
            for (int n2 = 0; n2 < 4; n2++) {
                uint4 b = *(const uint4*)
                    &sB[k8 * 1024 + (warpN * 4 + n2) * 128 + lane * 4];
#pragma unroll
                for (int mi = 0; mi < 2; mi++) {
                    mma_tf32(acc[mi][n2 * 2],     aF[mi], b.x, b.y);
                    mma_tf32(acc[mi][n2 * 2 + 1], aF[mi], b.z, b.w);
                }
            }
        }

        int cn = c + STAGES - 1;
        if (cn < NCH) issue(cn, cn % STAGES);
        asm volatile("cp.async.commit_group;");
        if (++stage == STAGES) stage = 0;
    }
    __syncthreads();   // pipe buffers dead; zs aliases them

    // ---- fused gate epilogue (two 64-row halves through shared) ----
#pragma unroll
    for (int half = 0; half < 2; half++) {
        if ((warpM >> 1) == half) {
#pragma unroll
            for (int mi = 0; mi < 2; mi++) {
                int zr = (warpM & 1) * 32 + mi * 16 + (lane >> 2);
#pragma unroll
                for (int ni = 0; ni < 8; ni++) {
                    int cN = warpN * 64 + ni * 8 + (lane & 3) * 2;
                    zs[zr][cN]         = acc[mi][ni][0];
                    zs[zr][cN + 1]     = acc[mi][ni][1];
                    zs[zr + 8][cN]     = acc[mi][ni][2];
                    zs[zr + 8][cN + 1] = acc[mi][ni][3];
                }
            }
        }
        __syncthreads();
#pragma unroll
        for (int e = 0; e < 8; e++) {
            int idx = tid + e * 256;          // 64*32 elems
            int m  = idx >> 5, nl = idx & 31;
            int gm = bx * 128 + half * 64 + m;
            int hc = by * 32 + nl;
            float zi = zs[m][nl]      + bias[hc];
            float zf = zs[m][32 + nl] + bias[H_SZ + hc];
            float zg = zs[m][64 + nl] + bias[2 * H_SZ + hc];
            float zo = zs[m][96 + nl] + bias[3 * H_SZ + hc];
            float ig = 1.f / (1.f + __expf(-zi));
            float fg = 1.f / (1.f + __expf(-zf));
            float gg = fmaxf(zg, 0.f);
            float og = 1.f / (1.f + __expf(-zo));
            int   ci = gm * H_SZ + hc;
            float cn = fg * g_c[ci] + ig * gg;
            g_c[ci] = cn;
            float h = og * fmaxf(cn, 0.f);
            // write h straight into next step's fragment layout
            int mt = gm >> 4, rr = gm & 15, k8 = hc >> 3, kk = hc & 7;
            int lw = (rr & 7) * 4 + (kk & 3);
            int v  = ((kk >> 2) << 1) | (rr >> 3);
            an[mt * 16384 + k8 * 128 + lw * 4 + v] = f2tf(h);
            if (t == T_SZ - 1) g_hl[ci] = h;
        }
        __syncthreads();
    }
}

// ---------------- dense head: y = h_T @ Wd + bd -----------------------------
__global__ void head_kernel(const float* __restrict__ Wd,
                            const float* __restrict__ bd,
                            float* __restrict__ out) {
    __shared__ float hs[H_SZ];
    const int row  = blockIdx.x;
    const int tid  = threadIdx.x;
    const int lane = tid & 31;
    const int w    = tid >> 5;
    for (int i = tid; i < H_SZ; i += 256) hs[i] = g_hl[row * H_SZ + i];
    __syncthreads();
    for (int o = w; o < OUT_SZ; o += 8) {
        float s = 0.f;
        for (int k = lane; k < H_SZ; k += 32) s += hs[k] * Wd[k * OUT_SZ + o];
#pragma unroll
        for (int off = 16; off; off >>= 1)
            s += __shfl_down_sync(0xffffffffu, s, off);
        if (lane == 0) out[row * OUT_SZ + o] = s + bd[o];
    }
}

extern "C" void kernel_launch(void* const* d_in, const int* in_sizes, int n_in,
                              void* d_out, int out_size) {
    const float* x    = (const float*)d_in[0];   // [2048,60,89]
    const float* W    = (const float*)d_in[1];   // [89,4096]
    const float* U    = (const float*)d_in[2];   // [1024,4096]
    const float* bias = (const float*)d_in[3];   // [4096]
    const float* Wd   = (const float*)d_in[4];   // [1024,30]
    const float* bd   = (const float*)d_in[5];   // [30]
    float* out = (float*)d_out;                  // [2048,30,1]

    static bool attr_set = false;
    if (!attr_set) {
        cudaFuncSetAttribute(lstm_step,
                             cudaFuncAttributeMaxDynamicSharedMemorySize,
                             STAGES * 32768);
        attr_set = true;
    }

    pack_B<<<17920, 256>>>(U, W);
    pack_x<<<46080, 256>>>(x);
    zero_state<<<4096, 256>>>();

    dim3 grid(B_SZ / 128, H_SZ / 32);            // 16 x 32 CTAs
    for (int t = 0; t < T_SZ; t++)
        lstm_step<<<grid, 256, STAGES * 32768>>>(bias, t);

    head_kernel<<<B_SZ, 256>>>(Wd, bd, out);
}